// round 14
// baseline (speedup 1.0000x reference)
#include <cuda_runtime.h>
#include <cuda_bf16.h>
#include <cstdint>

#define Bsz 16
#define Npt 4096
#define Kn  20
#define NROW (Bsz*Npt*Kn)      // 1,310,720 rows
#define HID 64
#define NEG_SLOPE 0.2f
#define EPSBN 1e-5f
#define NBLK (NROW/128)        // 10240 layer blocks

typedef unsigned int u32;
typedef unsigned long long u64;

// ---------------- scratch (device globals; no runtime allocation) ----------------
__device__ int   g_idx[Bsz*Npt*Kn];
__device__ float g_A  [Bsz*Npt*HID];
__device__ float g_Bv [Bsz*Npt*HID];
__device__ float g_z2 [(size_t)NROW*HID];
__device__ float g_pm [(size_t)NBLK*8*HID];
__device__ float g_sum[3][HID];
__device__ float g_sq [3][HID];
__device__ float g_scale[3][HID];
__device__ float g_shift[3][HID];
__device__ float g_bias [2][HID];                   // BN shift folded through W (per layer)

__device__ __forceinline__ float lrelu(float v){ return v > 0.f ? v : NEG_SLOPE*v; }

__device__ __forceinline__ int okey(float f){
    int i = __float_as_int(f);
    return i >= 0 ? i : (i ^ 0x7FFFFFFF);
}
__device__ __forceinline__ float ikey(int k){
    return __int_as_float(k >= 0 ? k : (k ^ 0x7FFFFFFF));
}

// ---------------- smem / HMMA helpers ----------------
__device__ __forceinline__ u32 smem_u32(const void* p){
    u32 a;
    asm("{ .reg .u64 t; cvta.to.shared.u64 t, %1; cvt.u32.u64 %0, t; }" : "=r"(a) : "l"(p));
    return a;
}
#define SWZ128(o) ((o) ^ (((o) >> 3) & 0x70))

#define LDSM_X4(r0,r1,r2,r3,addr) \
    asm volatile("ldmatrix.sync.aligned.m8n8.x4.shared.b16 {%0,%1,%2,%3}, [%4];" \
        : "=r"(r0), "=r"(r1), "=r"(r2), "=r"(r3) : "r"(addr))

#define MMA16816(d, a, b0_, b1_) \
    asm volatile("mma.sync.aligned.m16n8k16.row.col.f32.bf16.bf16.f32 " \
        "{%0,%1,%2,%3}, {%4,%5,%6,%7}, {%8,%9}, {%0,%1,%2,%3};" \
        : "+f"((d)[0]), "+f"((d)[1]), "+f"((d)[2]), "+f"((d)[3]) \
        : "r"((a)[0]), "r"((a)[1]), "r"((a)[2]), "r"((a)[3]), "r"(b0_), "r"(b1_))

// pack two floats to bf16x2 (v0 -> low half)
__device__ __forceinline__ u32 pack_bf2(float v0, float v1){
    u32 r;
    asm("cvt.rn.bf16x2.f32 %0, %1, %2;" : "=r"(r) : "f"(v1), "f"(v0));
    return r;
}
__device__ __forceinline__ float bf_round(float v){
    return __bfloat162float(__float2bfloat16(v));
}

// ---------------- init ----------------
__global__ void zero_stats_kernel(){
    int t = threadIdx.x;
    if (t < 3*HID){ ((float*)g_sum)[t] = 0.f; ((float*)g_sq)[t] = 0.f; }
}

// ---------------- per-point precompute for linearized layer 1 ----------------
__global__ void point_feats_kernel(const float* __restrict__ x, const float* __restrict__ W1){
    int p = blockIdx.x;
    int o = threadIdx.x;
    int b = p >> 12, n = p & (Npt-1);
    const float* xb = x + (size_t)b*3*Npt;
    float x0 = __ldg(xb + n), x1 = __ldg(xb + Npt + n), x2 = __ldg(xb + 2*Npt + n);
    float w0 = W1[o*6+0], w1 = W1[o*6+1], w2 = W1[o*6+2];
    float w3 = W1[o*6+3], w4 = W1[o*6+4], w5 = W1[o*6+5];
    g_A [p*HID+o] = x0*w0 + x1*w1 + x2*w2;
    g_Bv[p*HID+o] = x0*(w3-w0) + x1*(w4-w1) + x2*(w5-w2);
}

// ---------------- exact kNN (warp-coop top-20, 4-wide + OR ballot) + fused stats ----------------
// v' = 2*x.p - |p|^2 (query-constant sqi dropped: within-query ordering identical).
// key = (okey(v')^signflip)<<32 | (4095-j): v desc, then j asc == jax top_k ties.
// One OR-combined hot ballot per 128 candidates; rare path re-ballots each group
// against the CURRENT thr (thr only grows; rejects are exact, stale inserts were no-ops).
#define KNN_CHUNK 2048
#define KNN_THR   512

__global__ void __launch_bounds__(KNN_THR) knn_kernel(const float* __restrict__ x){
    __shared__ float4 pts[KNN_CHUNK];
    __shared__ float shs[HID], shq[HID];
    const unsigned FULL = 0xFFFFFFFFu;
    int b     = blockIdx.x >> 8;                    // 256 blocks per batch
    int qbase = (blockIdx.x & 255)*16;              // 16 queries (warps) per block
    int wid  = threadIdx.x >> 5;
    int lane = threadIdx.x & 31;
    const float* xb = x + (size_t)b*3*Npt;

    if (threadIdx.x < HID){ shs[threadIdx.x] = 0.f; shq[threadIdx.x] = 0.f; }

    int q = qbase + wid;
    float w0 = 2.f*xb[q], w1 = 2.f*xb[Npt+q], w2 = 2.f*xb[2*Npt+q];

    u64 key = 0ULL;
    u64 thr = 0ULL;

    for (int c0 = 0; c0 < Npt; c0 += KNN_CHUNK){
        __syncthreads();
        for (int t = threadIdx.x; t < KNN_CHUNK; t += KNN_THR){
            float px = xb[c0+t], py = xb[Npt+c0+t], pz = xb[2*Npt+c0+t];
            float nsq = -__fmaf_rn(pz, pz, __fmaf_rn(py, py, __fmul_rn(px, px)));
            pts[t] = make_float4(px, py, pz, nsq);
        }
        __syncthreads();

        for (int j0 = 0; j0 < KNN_CHUNK; j0 += 128){
            u64 cand[4];
            #pragma unroll
            for (int u = 0; u < 4; u++){
                int jl = j0 + u*32 + lane;
                float4 p = pts[jl];
                float v = __fmaf_rn(w0, p.x, __fmaf_rn(w1, p.y, __fmaf_rn(w2, p.z, p.w)));
                unsigned hi = (unsigned)okey(v) ^ 0x80000000u;
                cand[u] = ((u64)hi << 32) | (unsigned)(Npt-1-(c0+jl));
            }
            bool anyl = (cand[0] > thr) | (cand[1] > thr) | (cand[2] > thr) | (cand[3] > thr);
            if (__ballot_sync(FULL, anyl)){
                #pragma unroll
                for (int u = 0; u < 4; u++){
                    unsigned m = __ballot_sync(FULL, cand[u] > thr);
                    while (m){
                        int src = __ffs(m) - 1; m &= m - 1;
                        u64 kn = __shfl_sync(FULL, cand[u], src);
                        unsigned gt = __ballot_sync(FULL, key > kn) & 0xFFFFFu;
                        int pos = __popc(gt);
                        u64 up = __shfl_up_sync(FULL, key, 1);
                        if (lane < Kn){
                            if (lane == pos) key = kn;
                            else if (lane > pos) key = up;
                        }
                        thr = __shfl_sync(FULL, key, Kn-1);
                    }
                }
            }
        }
    }

    int myidx = (Npt-1) - (int)(key & 0xFFFFFFFFull);
    if (lane < Kn)
        g_idx[(b*Npt + q)*Kn + lane] = myidx;

    {   // fused stats of z1 = lrelu(A[nbr]+Bv[q]): 2 channels per lane
        int p = b*Npt + q;
        float2 bv = *(const float2*)(g_Bv + (size_t)p*HID + lane*2);
        float s0=0.f, s1=0.f, q0=0.f, q1=0.f;
        #pragma unroll
        for (int k = 0; k < Kn; k++){
            int nbr = __shfl_sync(FULL, myidx, k);
            float2 a = *(const float2*)(g_A + (size_t)((b<<12)+nbr)*HID + lane*2);
            float z0 = lrelu(a.x + bv.x), z1 = lrelu(a.y + bv.y);
            s0 += z0; q0 += z0*z0;
            s1 += z1; q1 += z1*z1;
        }
        atomicAdd(&shs[lane*2+0], s0); atomicAdd(&shq[lane*2+0], q0);
        atomicAdd(&shs[lane*2+1], s1); atomicAdd(&shq[lane*2+1], q1);
    }
    __syncthreads();
    if (threadIdx.x < HID){
        atomicAdd(&g_sum[0][threadIdx.x], shs[threadIdx.x]);
        atomicAdd(&g_sq [0][threadIdx.x], shq[threadIdx.x]);
    }
}

// ---------------- BN affine finalize (+ folded bias), 256 threads ----------------
__global__ void __launch_bounds__(256) finalize_kernel(int l, const float* __restrict__ gam,
                                                       const float* __restrict__ bet,
                                                       const float* __restrict__ Wn){
    __shared__ float part[4][HID];
    int t = threadIdx.x;
    int c = t & 63, seg = t >> 6;
    if (seg == 0){
        float inv = 1.f/(float)NROW;
        float mu  = g_sum[l][c]*inv;
        float var = g_sq[l][c]*inv - mu*mu;
        float sc  = gam[c]*rsqrtf(var + EPSBN);
        g_scale[l][c] = sc;
        g_shift[l][c] = bet[c] - mu*sc;
    }
    if (Wn){
        __syncthreads();
        float acc = 0.f;
        #pragma unroll
        for (int k = seg*16; k < seg*16+16; k++)
            acc += g_shift[l][k] * Wn[c*HID + k];
        part[seg][c] = acc;
        __syncthreads();
        if (seg == 0)
            g_bias[l][c] = part[0][c] + part[1][c] + part[2][c] + part[3][c];
    }
}

// ---------------- HMMA layer: raw z tiles (bf16 hi/lo) x (W*scale) tiles + bias ----------------
#define INSP 129
#define SMEM_DYN (1024 + 16384*2 + 8192*2)

template<int MODE>
__global__ void __launch_bounds__(256) layer_mm(const float* __restrict__ W){
    extern __shared__ char dsm[];
    __shared__ float shs[HID], shq[HID], sbias[HID];
    __shared__ int spm[8][65];

    u32 raw = smem_u32(dsm);
    u32 ab  = (raw + 1023u) & ~1023u;
    u32 A_hi = ab, A_lo = ab + 16384, B_hi = ab + 32768, B_lo = ab + 40960;
    float* ins = (float*)(dsm + (ab - raw));

    int tid = threadIdx.x;
    int w = tid >> 5, lane = tid & 31;
    int row0 = blockIdx.x * 128;

    if (tid < HID){ shs[tid] = 0.f; sbias[tid] = g_bias[MODE][tid]; }
    if (tid >= HID && tid < 2*HID) shq[tid-HID] = 0.f;
    if (MODE == 1){
        for (int u = tid; u < 8*65; u += 256) ((int*)spm)[u] = 0x80000000;
    }

    // ---- B tiles: W'[o][c] = W[o][c]*scale[c], bf16 hi/lo, SW128 ----
    {
        int o = tid >> 2, cs = (tid & 3)*16;
        const float4* wr = (const float4*)(W + o*HID + cs);
        float4 q0 = wr[0], q1 = wr[1], q2 = wr[2], q3 = wr[3];
        float wv[16] = {q0.x,q0.y,q0.z,q0.w, q1.x,q1.y,q1.z,q1.w,
                        q2.x,q2.y,q2.z,q2.w, q3.x,q3.y,q3.z,q3.w};
        #pragma unroll
        for (int i = 0; i < 8; i++){
            int c0 = cs + 2*i;
            float v0 = wv[2*i]   * g_scale[MODE][c0];
            float v1 = wv[2*i+1] * g_scale[MODE][c0+1];
            float h0 = bf_round(v0), h1 = bf_round(v1);
            u32 hp = pack_bf2(v0, v1);
            u32 lp = pack_bf2(v0 - h0, v1 - h1);
            u32 off = SWZ128((u32)(o*128 + c0*2));
            asm volatile("st.shared.b32 [%0], %1;" :: "r"(B_hi + off), "r"(hp) : "memory");
            asm volatile("st.shared.b32 [%0], %1;" :: "r"(B_lo + off), "r"(lp) : "memory");
        }
    }

    // ---- A tiles: raw z rows, bf16 hi/lo, SW128 (2 threads/row) ----
    {
        int lr = tid >> 1, h = (tid & 1)*32;
        int row = row0 + lr;
        float v[32];
        if (MODE == 0){
            int pnt = row / Kn;
            int b = pnt >> 12;
            int nbr = g_idx[row];
            const float4* P0 = (const float4*)(g_A  + (size_t)((b<<12)+nbr)*HID + h);
            const float4* P1 = (const float4*)(g_Bv + (size_t)pnt*HID + h);
            #pragma unroll
            for (int u = 0; u < 8; u++){
                float4 a = P0[u], bvv = P1[u];
                v[u*4+0] = lrelu(a.x+bvv.x);
                v[u*4+1] = lrelu(a.y+bvv.y);
                v[u*4+2] = lrelu(a.z+bvv.z);
                v[u*4+3] = lrelu(a.w+bvv.w);
            }
        } else {
            const float4* Z = (const float4*)(g_z2 + (size_t)row*HID + h);
            #pragma unroll
            for (int u = 0; u < 8; u++){
                float4 zz = Z[u];
                v[u*4+0] = zz.x; v[u*4+1] = zz.y; v[u*4+2] = zz.z; v[u*4+3] = zz.w;
            }
        }
        #pragma unroll
        for (int i = 0; i < 16; i++){
            float v0 = v[2*i], v1 = v[2*i+1];
            float h0 = bf_round(v0), h1 = bf_round(v1);
            u32 hp = pack_bf2(v0, v1);
            u32 lp = pack_bf2(v0 - h0, v1 - h1);
            u32 off = SWZ128((u32)(lr*128 + (h + 2*i)*2));
            asm volatile("st.shared.b32 [%0], %1;" :: "r"(A_hi + off), "r"(hp) : "memory");
            asm volatile("st.shared.b32 [%0], %1;" :: "r"(A_lo + off), "r"(lp) : "memory");
        }
    }
    __syncthreads();

    // ---- mainloop: per-warp 16-row stripe, 96 HMMA, 32 B-LDSM (B_hi reused for Ah & Al) ----
    float acc[8][4];
    #pragma unroll
    for (int nt = 0; nt < 8; nt++)
        #pragma unroll
        for (int j = 0; j < 4; j++) acc[nt][j] = 0.f;

    int arow = (w<<4) + (lane & 7) + ((lane >> 3) & 1) * 8;
    int acb  = ((lane >> 4) & 1) * 16;
    u32 Ah[4][4], Al[4][4];
    #pragma unroll
    for (int kt = 0; kt < 4; kt++){
        u32 aoff = SWZ128((u32)(arow*128 + kt*32 + acb));
        LDSM_X4(Ah[kt][0], Ah[kt][1], Ah[kt][2], Ah[kt][3], A_hi + aoff);
        LDSM_X4(Al[kt][0], Al[kt][1], Al[kt][2], Al[kt][3], A_lo + aoff);
    }

    int brow = (lane & 7) + ((lane >> 4) & 1) * 8;
    int bcb  = ((lane >> 3) & 1) * 16;

    #pragma unroll
    for (int nt2 = 0; nt2 < 4; nt2++){
        #pragma unroll
        for (int kt = 0; kt < 4; kt++){
            u32 boff = SWZ128((u32)((nt2*16 + brow)*128 + kt*32 + bcb));
            u32 b0, b1, b2, b3;
            LDSM_X4(b0, b1, b2, b3, B_hi + boff);     // B_hi: feeds Ah and Al products
            MMA16816(acc[nt2*2],   Ah[kt], b0, b1);
            MMA16816(acc[nt2*2+1], Ah[kt], b2, b3);
            MMA16816(acc[nt2*2],   Al[kt], b0, b1);
            MMA16816(acc[nt2*2+1], Al[kt], b2, b3);
            u32 c0_, c1_, c2_, c3_;
            LDSM_X4(c0_, c1_, c2_, c3_, B_lo + boff); // B_lo: Ah product only
            MMA16816(acc[nt2*2],   Ah[kt], c0_, c1_);
            MMA16816(acc[nt2*2+1], Ah[kt], c2_, c3_);
        }
    }
    __syncthreads();

    // ---- epilogue: bias + lrelu, scatter to ins[c][row] ----
    {
        int r0 = (w<<4) + (lane >> 2);
        #pragma unroll
        for (int nt = 0; nt < 8; nt++){
            int c0 = nt*8 + (lane & 3)*2;
            float b0v = sbias[c0], b1v = sbias[c0+1];
            ins[c0*INSP + r0]         = lrelu(acc[nt][0] + b0v);
            ins[(c0+1)*INSP + r0]     = lrelu(acc[nt][1] + b1v);
            ins[c0*INSP + r0 + 8]     = lrelu(acc[nt][2] + b0v);
            ins[(c0+1)*INSP + r0 + 8] = lrelu(acc[nt][3] + b1v);
        }
    }
    __syncthreads();

    // ---- stats / (store | max) phase ----
    int tr = tid >> 4;
    int tc = (tid & 15)*4;

    const float NEG_INF = -__int_as_float(0x7f800000);
    int slotbase = row0 / Kn;
    int sA = (row0 + tr*8) / Kn - slotbase;
    float amax[4] = {NEG_INF,NEG_INF,NEG_INF,NEG_INF};
    float bmax[4] = {NEG_INF,NEG_INF,NEG_INF,NEG_INF};

    float ls[4] = {0,0,0,0}, lq[4] = {0,0,0,0};
    #pragma unroll
    for (int rp = 0; rp < 4; rp++){
        int r0l = tr*8 + 2*rp;
        float zlo[4], zhi[4];
        #pragma unroll
        for (int j = 0; j < 4; j++){
            zlo[j] = ins[(tc+j)*INSP + r0l];
            zhi[j] = ins[(tc+j)*INSP + r0l + 1];
            ls[j] += zlo[j] + zhi[j];
            lq[j] += zlo[j]*zlo[j] + zhi[j]*zhi[j];
        }
        int rlo = row0 + r0l;
        if (MODE == 0){
            *(float4*)(g_z2 + (size_t)rlo*HID + tc)     = make_float4(zlo[0],zlo[1],zlo[2],zlo[3]);
            *(float4*)(g_z2 + (size_t)(rlo+1)*HID + tc) = make_float4(zhi[0],zhi[1],zhi[2],zhi[3]);
        } else {
            bool lo_inA = (rlo    / Kn - slotbase) == sA;
            bool hi_inA = ((rlo+1)/ Kn - slotbase) == sA;
            #pragma unroll
            for (int j = 0; j < 4; j++){
                amax[j] = lo_inA ? fmaxf(amax[j], zlo[j]) : amax[j];
                bmax[j] = lo_inA ? bmax[j] : fmaxf(bmax[j], zlo[j]);
                amax[j] = hi_inA ? fmaxf(amax[j], zhi[j]) : amax[j];
                bmax[j] = hi_inA ? bmax[j] : fmaxf(bmax[j], zhi[j]);
            }
        }
    }
    if (MODE == 1){
        int sB = sA + 1;
        #pragma unroll
        for (int j = 0; j < 4; j++){
            atomicMax(&spm[sA][tc+j], okey(amax[j]));
            if (sB < 8) atomicMax(&spm[sB][tc+j], okey(bmax[j]));
        }
    }
    #pragma unroll
    for (int j = 0; j < 4; j++){
        atomicAdd(&shs[tc+j], ls[j]);
        atomicAdd(&shq[tc+j], lq[j]);
    }
    __syncthreads();
    if (tid < HID){
        atomicAdd(&g_sum[MODE+1][tid], shs[tid]);
        atomicAdd(&g_sq [MODE+1][tid], shq[tid]);
    }
    if (MODE == 1){
        for (int u = tid; u < 8*HID; u += 256)
            g_pm[(size_t)blockIdx.x*(8*HID) + u] = ikey(spm[u>>6][u&63]);
    }
}

// ---------------- combine partial maxes, BN3 affine, transpose to [B,64,N] ----------------
__global__ void __launch_bounds__(256) final_kernel(float* __restrict__ out){
    __shared__ float sh[HID][65];
    int pt0 = blockIdx.x * 64;
    int ch = threadIdx.x & 63;
    float sc = g_scale[2][ch], tt = g_shift[2][ch];
    for (int pl = threadIdx.x >> 6; pl < 64; pl += 4){
        int p = pt0 + pl;
        int r0 = p*Kn, r1 = r0 + Kn - 1;
        int b0 = r0 >> 7, b1 = r1 >> 7;
        int s0 = p - (b0 << 7)/Kn;
        float m = g_pm[(size_t)b0*(8*HID) + s0*HID + ch];
        if (b1 != b0){
            int s1 = p - (b1 << 7)/Kn;
            m = fmaxf(m, g_pm[(size_t)b1*(8*HID) + s1*HID + ch]);
        }
        sh[ch][pl] = m*sc + tt;
    }
    __syncthreads();
    int b = pt0 >> 12, n0 = pt0 & (Npt-1);
    int n = threadIdx.x & 63;
    for (int ol = threadIdx.x >> 6; ol < 64; ol += 4)
        out[((size_t)b*HID + ol)*Npt + n0 + n] = sh[ol][n];
}

// ---------------- launch ----------------
extern "C" void kernel_launch(void* const* d_in, const int* in_sizes, int n_in,
                              void* d_out, int out_size){
    const float* x  = (const float*)d_in[0];
    const float* W1 = (const float*)d_in[1];
    const float* W2 = (const float*)d_in[2];
    const float* W3 = (const float*)d_in[3];
    const float* g1 = (const float*)d_in[4];
    const float* b1 = (const float*)d_in[5];
    const float* g2 = (const float*)d_in[6];
    const float* b2 = (const float*)d_in[7];
    float* out = (float*)d_out;

    cudaFuncSetAttribute(layer_mm<0>, cudaFuncAttributeMaxDynamicSharedMemorySize, SMEM_DYN);
    cudaFuncSetAttribute(layer_mm<1>, cudaFuncAttributeMaxDynamicSharedMemorySize, SMEM_DYN);

    zero_stats_kernel<<<1, 3*HID>>>();
    point_feats_kernel<<<Bsz*Npt, HID>>>(x, W1);
    knn_kernel<<<Bsz*256, KNN_THR>>>(x);           // includes fused layer-1 stats
    finalize_kernel<<<1, 256>>>(0, g1, b1, W2);
    layer_mm<0><<<NBLK, 256, SMEM_DYN>>>(W2);
    finalize_kernel<<<1, 256>>>(1, g1, b1, W3);
    layer_mm<1><<<NBLK, 256, SMEM_DYN>>>(W3);
    finalize_kernel<<<1, 256>>>(2, g2, b2, nullptr);
    final_kernel<<<Bsz*Npt/64, 256>>>(out);
}

// round 15
// speedup vs baseline: 1.0240x; 1.0240x over previous
#include <cuda_runtime.h>
#include <cuda_bf16.h>
#include <cstdint>

#define Bsz 16
#define Npt 4096
#define Kn  20
#define NROW (Bsz*Npt*Kn)      // 1,310,720 rows
#define HID 64
#define NEG_SLOPE 0.2f
#define EPSBN 1e-5f
#define NBLK (NROW/128)        // 10240 layer blocks

typedef unsigned int u32;
typedef unsigned long long u64;

// ---------------- scratch (device globals; no runtime allocation) ----------------
__device__ int   g_idx[Bsz*Npt*Kn];
__device__ float g_A  [Bsz*Npt*HID];
__device__ float g_Bv [Bsz*Npt*HID];
__device__ float g_z2 [(size_t)NROW*HID];
__device__ float g_pm [(size_t)NBLK*8*HID];
__device__ float g_sum[3][HID];
__device__ float g_sq [3][HID];
__device__ float g_scale[3][HID];
__device__ float g_shift[3][HID];
__device__ float g_bias [2][HID];                   // BN shift folded through W (per layer)

__device__ __forceinline__ float lrelu(float v){ return v > 0.f ? v : NEG_SLOPE*v; }

__device__ __forceinline__ int okey(float f){
    int i = __float_as_int(f);
    return i >= 0 ? i : (i ^ 0x7FFFFFFF);
}
__device__ __forceinline__ float ikey(int k){
    return __int_as_float(k >= 0 ? k : (k ^ 0x7FFFFFFF));
}

// ---------------- smem / HMMA helpers ----------------
__device__ __forceinline__ u32 smem_u32(const void* p){
    u32 a;
    asm("{ .reg .u64 t; cvta.to.shared.u64 t, %1; cvt.u32.u64 %0, t; }" : "=r"(a) : "l"(p));
    return a;
}
#define SWZ128(o) ((o) ^ (((o) >> 3) & 0x70))

#define LDSM_X4(r0,r1,r2,r3,addr) \
    asm volatile("ldmatrix.sync.aligned.m8n8.x4.shared.b16 {%0,%1,%2,%3}, [%4];" \
        : "=r"(r0), "=r"(r1), "=r"(r2), "=r"(r3) : "r"(addr))

#define MMA16816(d, a, b0_, b1_) \
    asm volatile("mma.sync.aligned.m16n8k16.row.col.f32.bf16.bf16.f32 " \
        "{%0,%1,%2,%3}, {%4,%5,%6,%7}, {%8,%9}, {%0,%1,%2,%3};" \
        : "+f"((d)[0]), "+f"((d)[1]), "+f"((d)[2]), "+f"((d)[3]) \
        : "r"((a)[0]), "r"((a)[1]), "r"((a)[2]), "r"((a)[3]), "r"(b0_), "r"(b1_))

// pack two floats to bf16x2 (v0 -> low half)
__device__ __forceinline__ u32 pack_bf2(float v0, float v1){
    u32 r;
    asm("cvt.rn.bf16x2.f32 %0, %1, %2;" : "=r"(r) : "f"(v1), "f"(v0));
    return r;
}
__device__ __forceinline__ float bf_round(float v){
    return __bfloat162float(__float2bfloat16(v));
}

// ---------------- init ----------------
__global__ void zero_stats_kernel(){
    int t = threadIdx.x;
    if (t < 3*HID){ ((float*)g_sum)[t] = 0.f; ((float*)g_sq)[t] = 0.f; }
}

// no-op launch index shims: put knn_kernel at launch index 5 for the ncu
// capture window (-s 5 -c 1). Deterministic, graph-capturable, ~1us each.
__global__ void dummy_kernel(){}

// ---------------- per-point precompute for linearized layer 1 (4 pts/256-thr block) ----------------
__global__ void __launch_bounds__(256) point_feats_kernel(const float* __restrict__ x,
                                                          const float* __restrict__ W1){
    int p = blockIdx.x*4 + (threadIdx.x >> 6);     // global point 0..65535
    int o = threadIdx.x & 63;                      // channel 0..63
    int b = p >> 12, n = p & (Npt-1);
    const float* xb = x + (size_t)b*3*Npt;
    float x0 = __ldg(xb + n), x1 = __ldg(xb + Npt + n), x2 = __ldg(xb + 2*Npt + n);
    float w0 = W1[o*6+0], w1 = W1[o*6+1], w2 = W1[o*6+2];
    float w3 = W1[o*6+3], w4 = W1[o*6+4], w5 = W1[o*6+5];
    g_A [p*HID+o] = x0*w0 + x1*w1 + x2*w2;
    g_Bv[p*HID+o] = x0*(w3-w0) + x1*(w4-w1) + x2*(w5-w2);
}

// ---------------- exact kNN (warp-coop top-20, 2-wide ILP = R13 best) + fused stats ----------------
// v' = 2*x.p - |p|^2 (query-constant sqi dropped: within-query ordering identical).
// key = (okey(v')^signflip)<<32 | (4095-j): v desc, then j asc == jax top_k ties.
#define KNN_CHUNK 2048
#define KNN_THR   512

__global__ void __launch_bounds__(KNN_THR) knn_kernel(const float* __restrict__ x){
    __shared__ float4 pts[KNN_CHUNK];
    __shared__ float shs[HID], shq[HID];
    const unsigned FULL = 0xFFFFFFFFu;
    int b     = blockIdx.x >> 8;                    // 256 blocks per batch
    int qbase = (blockIdx.x & 255)*16;              // 16 queries (warps) per block
    int wid  = threadIdx.x >> 5;
    int lane = threadIdx.x & 31;
    const float* xb = x + (size_t)b*3*Npt;

    if (threadIdx.x < HID){ shs[threadIdx.x] = 0.f; shq[threadIdx.x] = 0.f; }

    int q = qbase + wid;
    float w0 = 2.f*xb[q], w1 = 2.f*xb[Npt+q], w2 = 2.f*xb[2*Npt+q];

    u64 key = 0ULL;
    u64 thr = 0ULL;

    for (int c0 = 0; c0 < Npt; c0 += KNN_CHUNK){
        __syncthreads();
        for (int t = threadIdx.x; t < KNN_CHUNK; t += KNN_THR){
            float px = xb[c0+t], py = xb[Npt+c0+t], pz = xb[2*Npt+c0+t];
            float nsq = -__fmaf_rn(pz, pz, __fmaf_rn(py, py, __fmul_rn(px, px)));
            pts[t] = make_float4(px, py, pz, nsq);
        }
        __syncthreads();

        for (int j0 = 0; j0 < KNN_CHUNK; j0 += 64){
            float4 p1 = pts[j0 + lane];
            float4 p2 = pts[j0 + 32 + lane];
            float v1 = __fmaf_rn(w0, p1.x, __fmaf_rn(w1, p1.y, __fmaf_rn(w2, p1.z, p1.w)));
            float v2 = __fmaf_rn(w0, p2.x, __fmaf_rn(w1, p2.y, __fmaf_rn(w2, p2.z, p2.w)));
            unsigned h1 = (unsigned)okey(v1) ^ 0x80000000u;
            unsigned h2 = (unsigned)okey(v2) ^ 0x80000000u;
            u64 cand1 = ((u64)h1 << 32) | (unsigned)(Npt-1-(c0+j0+lane));
            u64 cand2 = ((u64)h2 << 32) | (unsigned)(Npt-1-(c0+j0+32+lane));
            unsigned m1 = __ballot_sync(FULL, cand1 > thr);
            unsigned m2 = __ballot_sync(FULL, cand2 > thr);
            while (m1){
                int src = __ffs(m1) - 1; m1 &= m1 - 1;
                u64 kn = __shfl_sync(FULL, cand1, src);
                unsigned gt = __ballot_sync(FULL, key > kn) & 0xFFFFFu;
                int pos = __popc(gt);
                u64 up = __shfl_up_sync(FULL, key, 1);
                if (lane < Kn){
                    if (lane == pos) key = kn;
                    else if (lane > pos) key = up;
                }
                thr = __shfl_sync(FULL, key, Kn-1);
            }
            while (m2){
                int src = __ffs(m2) - 1; m2 &= m2 - 1;
                u64 kn = __shfl_sync(FULL, cand2, src);
                unsigned gt = __ballot_sync(FULL, key > kn) & 0xFFFFFu;
                int pos = __popc(gt);
                u64 up = __shfl_up_sync(FULL, key, 1);
                if (lane < Kn){
                    if (lane == pos) key = kn;
                    else if (lane > pos) key = up;
                }
                thr = __shfl_sync(FULL, key, Kn-1);
            }
        }
    }

    int myidx = (Npt-1) - (int)(key & 0xFFFFFFFFull);
    if (lane < Kn)
        g_idx[(b*Npt + q)*Kn + lane] = myidx;

    {   // fused stats of z1 = lrelu(A[nbr]+Bv[q]): 2 channels per lane
        int p = b*Npt + q;
        float2 bv = *(const float2*)(g_Bv + (size_t)p*HID + lane*2);
        float s0=0.f, s1=0.f, q0=0.f, q1=0.f;
        #pragma unroll
        for (int k = 0; k < Kn; k++){
            int nbr = __shfl_sync(FULL, myidx, k);
            float2 a = *(const float2*)(g_A + (size_t)((b<<12)+nbr)*HID + lane*2);
            float z0 = lrelu(a.x + bv.x), z1 = lrelu(a.y + bv.y);
            s0 += z0; q0 += z0*z0;
            s1 += z1; q1 += z1*z1;
        }
        atomicAdd(&shs[lane*2+0], s0); atomicAdd(&shq[lane*2+0], q0);
        atomicAdd(&shs[lane*2+1], s1); atomicAdd(&shq[lane*2+1], q1);
    }
    __syncthreads();
    if (threadIdx.x < HID){
        atomicAdd(&g_sum[0][threadIdx.x], shs[threadIdx.x]);
        atomicAdd(&g_sq [0][threadIdx.x], shq[threadIdx.x]);
    }
}

// ---------------- BN affine finalize (+ folded bias), 256 threads ----------------
__global__ void __launch_bounds__(256) finalize_kernel(int l, const float* __restrict__ gam,
                                                       const float* __restrict__ bet,
                                                       const float* __restrict__ Wn){
    __shared__ float part[4][HID];
    int t = threadIdx.x;
    int c = t & 63, seg = t >> 6;
    if (seg == 0){
        float inv = 1.f/(float)NROW;
        float mu  = g_sum[l][c]*inv;
        float var = g_sq[l][c]*inv - mu*mu;
        float sc  = gam[c]*rsqrtf(var + EPSBN);
        g_scale[l][c] = sc;
        g_shift[l][c] = bet[c] - mu*sc;
    }
    if (Wn){
        __syncthreads();
        float acc = 0.f;
        #pragma unroll
        for (int k = seg*16; k < seg*16+16; k++)
            acc += g_shift[l][k] * Wn[c*HID + k];
        part[seg][c] = acc;
        __syncthreads();
        if (seg == 0)
            g_bias[l][c] = part[0][c] + part[1][c] + part[2][c] + part[3][c];
    }
}

// ---------------- HMMA layer: raw z tiles (bf16 hi/lo) x (W*scale) tiles + bias ----------------
#define INSP 129
#define SMEM_DYN (1024 + 16384*2 + 8192*2)

template<int MODE>
__global__ void __launch_bounds__(256) layer_mm(const float* __restrict__ W){
    extern __shared__ char dsm[];
    __shared__ float shs[HID], shq[HID], sbias[HID];
    __shared__ int spm[8][65];

    u32 raw = smem_u32(dsm);
    u32 ab  = (raw + 1023u) & ~1023u;
    u32 A_hi = ab, A_lo = ab + 16384, B_hi = ab + 32768, B_lo = ab + 40960;
    float* ins = (float*)(dsm + (ab - raw));

    int tid = threadIdx.x;
    int w = tid >> 5, lane = tid & 31;
    int row0 = blockIdx.x * 128;

    if (tid < HID){ shs[tid] = 0.f; sbias[tid] = g_bias[MODE][tid]; }
    if (tid >= HID && tid < 2*HID) shq[tid-HID] = 0.f;
    if (MODE == 1){
        for (int u = tid; u < 8*65; u += 256) ((int*)spm)[u] = 0x80000000;
    }

    // ---- B tiles: W'[o][c] = W[o][c]*scale[c], bf16 hi/lo, SW128 ----
    {
        int o = tid >> 2, cs = (tid & 3)*16;
        const float4* wr = (const float4*)(W + o*HID + cs);
        float4 q0 = wr[0], q1 = wr[1], q2 = wr[2], q3 = wr[3];
        float wv[16] = {q0.x,q0.y,q0.z,q0.w, q1.x,q1.y,q1.z,q1.w,
                        q2.x,q2.y,q2.z,q2.w, q3.x,q3.y,q3.z,q3.w};
        #pragma unroll
        for (int i = 0; i < 8; i++){
            int c0 = cs + 2*i;
            float v0 = wv[2*i]   * g_scale[MODE][c0];
            float v1 = wv[2*i+1] * g_scale[MODE][c0+1];
            float h0 = bf_round(v0), h1 = bf_round(v1);
            u32 hp = pack_bf2(v0, v1);
            u32 lp = pack_bf2(v0 - h0, v1 - h1);
            u32 off = SWZ128((u32)(o*128 + c0*2));
            asm volatile("st.shared.b32 [%0], %1;" :: "r"(B_hi + off), "r"(hp) : "memory");
            asm volatile("st.shared.b32 [%0], %1;" :: "r"(B_lo + off), "r"(lp) : "memory");
        }
    }

    // ---- A tiles: raw z rows, bf16 hi/lo, SW128 (2 threads/row) ----
    {
        int lr = tid >> 1, h = (tid & 1)*32;
        int row = row0 + lr;
        float v[32];
        if (MODE == 0){
            int pnt = row / Kn;
            int b = pnt >> 12;
            int nbr = g_idx[row];
            const float4* P0 = (const float4*)(g_A  + (size_t)((b<<12)+nbr)*HID + h);
            const float4* P1 = (const float4*)(g_Bv + (size_t)pnt*HID + h);
            #pragma unroll
            for (int u = 0; u < 8; u++){
                float4 a = P0[u], bvv = P1[u];
                v[u*4+0] = lrelu(a.x+bvv.x);
                v[u*4+1] = lrelu(a.y+bvv.y);
                v[u*4+2] = lrelu(a.z+bvv.z);
                v[u*4+3] = lrelu(a.w+bvv.w);
            }
        } else {
            const float4* Z = (const float4*)(g_z2 + (size_t)row*HID + h);
            #pragma unroll
            for (int u = 0; u < 8; u++){
                float4 zz = Z[u];
                v[u*4+0] = zz.x; v[u*4+1] = zz.y; v[u*4+2] = zz.z; v[u*4+3] = zz.w;
            }
        }
        #pragma unroll
        for (int i = 0; i < 16; i++){
            float v0 = v[2*i], v1 = v[2*i+1];
            float h0 = bf_round(v0), h1 = bf_round(v1);
            u32 hp = pack_bf2(v0, v1);
            u32 lp = pack_bf2(v0 - h0, v1 - h1);
            u32 off = SWZ128((u32)(lr*128 + (h + 2*i)*2));
            asm volatile("st.shared.b32 [%0], %1;" :: "r"(A_hi + off), "r"(hp) : "memory");
            asm volatile("st.shared.b32 [%0], %1;" :: "r"(A_lo + off), "r"(lp) : "memory");
        }
    }
    __syncthreads();

    // ---- mainloop: per-warp 16-row stripe, 96 HMMA, 32 B-LDSM (B_hi reused for Ah & Al) ----
    float acc[8][4];
    #pragma unroll
    for (int nt = 0; nt < 8; nt++)
        #pragma unroll
        for (int j = 0; j < 4; j++) acc[nt][j] = 0.f;

    int arow = (w<<4) + (lane & 7) + ((lane >> 3) & 1) * 8;
    int acb  = ((lane >> 4) & 1) * 16;
    u32 Ah[4][4], Al[4][4];
    #pragma unroll
    for (int kt = 0; kt < 4; kt++){
        u32 aoff = SWZ128((u32)(arow*128 + kt*32 + acb));
        LDSM_X4(Ah[kt][0], Ah[kt][1], Ah[kt][2], Ah[kt][3], A_hi + aoff);
        LDSM_X4(Al[kt][0], Al[kt][1], Al[kt][2], Al[kt][3], A_lo + aoff);
    }

    int brow = (lane & 7) + ((lane >> 4) & 1) * 8;
    int bcb  = ((lane >> 3) & 1) * 16;

    #pragma unroll
    for (int nt2 = 0; nt2 < 4; nt2++){
        #pragma unroll
        for (int kt = 0; kt < 4; kt++){
            u32 boff = SWZ128((u32)((nt2*16 + brow)*128 + kt*32 + bcb));
            u32 b0, b1, b2, b3;
            LDSM_X4(b0, b1, b2, b3, B_hi + boff);     // B_hi: feeds Ah and Al products
            MMA16816(acc[nt2*2],   Ah[kt], b0, b1);
            MMA16816(acc[nt2*2+1], Ah[kt], b2, b3);
            MMA16816(acc[nt2*2],   Al[kt], b0, b1);
            MMA16816(acc[nt2*2+1], Al[kt], b2, b3);
            u32 c0_, c1_, c2_, c3_;
            LDSM_X4(c0_, c1_, c2_, c3_, B_lo + boff); // B_lo: Ah product only
            MMA16816(acc[nt2*2],   Ah[kt], c0_, c1_);
            MMA16816(acc[nt2*2+1], Ah[kt], c2_, c3_);
        }
    }
    __syncthreads();

    // ---- epilogue: bias + lrelu, scatter to ins[c][row] ----
    {
        int r0 = (w<<4) + (lane >> 2);
        #pragma unroll
        for (int nt = 0; nt < 8; nt++){
            int c0 = nt*8 + (lane & 3)*2;
            float b0v = sbias[c0], b1v = sbias[c0+1];
            ins[c0*INSP + r0]         = lrelu(acc[nt][0] + b0v);
            ins[(c0+1)*INSP + r0]     = lrelu(acc[nt][1] + b1v);
            ins[c0*INSP + r0 + 8]     = lrelu(acc[nt][2] + b0v);
            ins[(c0+1)*INSP + r0 + 8] = lrelu(acc[nt][3] + b1v);
        }
    }
    __syncthreads();

    // ---- stats / (store | max) phase ----
    int tr = tid >> 4;
    int tc = (tid & 15)*4;

    const float NEG_INF = -__int_as_float(0x7f800000);
    int slotbase = row0 / Kn;
    int sA = (row0 + tr*8) / Kn - slotbase;
    float amax[4] = {NEG_INF,NEG_INF,NEG_INF,NEG_INF};
    float bmax[4] = {NEG_INF,NEG_INF,NEG_INF,NEG_INF};

    float ls[4] = {0,0,0,0}, lq[4] = {0,0,0,0};
    #pragma unroll
    for (int rp = 0; rp < 4; rp++){
        int r0l = tr*8 + 2*rp;
        float zlo[4], zhi[4];
        #pragma unroll
        for (int j = 0; j < 4; j++){
            zlo[j] = ins[(tc+j)*INSP + r0l];
            zhi[j] = ins[(tc+j)*INSP + r0l + 1];
            ls[j] += zlo[j] + zhi[j];
            lq[j] += zlo[j]*zlo[j] + zhi[j]*zhi[j];
        }
        int rlo = row0 + r0l;
        if (MODE == 0){
            *(float4*)(g_z2 + (size_t)rlo*HID + tc)     = make_float4(zlo[0],zlo[1],zlo[2],zlo[3]);
            *(float4*)(g_z2 + (size_t)(rlo+1)*HID + tc) = make_float4(zhi[0],zhi[1],zhi[2],zhi[3]);
        } else {
            bool lo_inA = (rlo    / Kn - slotbase) == sA;
            bool hi_inA = ((rlo+1)/ Kn - slotbase) == sA;
            #pragma unroll
            for (int j = 0; j < 4; j++){
                amax[j] = lo_inA ? fmaxf(amax[j], zlo[j]) : amax[j];
                bmax[j] = lo_inA ? bmax[j] : fmaxf(bmax[j], zlo[j]);
                amax[j] = hi_inA ? fmaxf(amax[j], zhi[j]) : amax[j];
                bmax[j] = hi_inA ? bmax[j] : fmaxf(bmax[j], zhi[j]);
            }
        }
    }
    if (MODE == 1){
        int sB = sA + 1;
        #pragma unroll
        for (int j = 0; j < 4; j++){
            atomicMax(&spm[sA][tc+j], okey(amax[j]));
            if (sB < 8) atomicMax(&spm[sB][tc+j], okey(bmax[j]));
        }
    }
    #pragma unroll
    for (int j = 0; j < 4; j++){
        atomicAdd(&shs[tc+j], ls[j]);
        atomicAdd(&shq[tc+j], lq[j]);
    }
    __syncthreads();
    if (tid < HID){
        atomicAdd(&g_sum[MODE+1][tid], shs[tid]);
        atomicAdd(&g_sq [MODE+1][tid], shq[tid]);
    }
    if (MODE == 1){
        for (int u = tid; u < 8*HID; u += 256)
            g_pm[(size_t)blockIdx.x*(8*HID) + u] = ikey(spm[u>>6][u&63]);
    }
}

// ---------------- combine partial maxes, BN3 affine, transpose to [B,64,N] ----------------
__global__ void __launch_bounds__(256) final_kernel(float* __restrict__ out){
    __shared__ float sh[HID][65];
    int pt0 = blockIdx.x * 64;
    int ch = threadIdx.x & 63;
    float sc = g_scale[2][ch], tt = g_shift[2][ch];
    for (int pl = threadIdx.x >> 6; pl < 64; pl += 4){
        int p = pt0 + pl;
        int r0 = p*Kn, r1 = r0 + Kn - 1;
        int b0 = r0 >> 7, b1 = r1 >> 7;
        int s0 = p - (b0 << 7)/Kn;
        float m = g_pm[(size_t)b0*(8*HID) + s0*HID + ch];
        if (b1 != b0){
            int s1 = p - (b1 << 7)/Kn;
            m = fmaxf(m, g_pm[(size_t)b1*(8*HID) + s1*HID + ch]);
        }
        sh[ch][pl] = m*sc + tt;
    }
    __syncthreads();
    int b = pt0 >> 12, n0 = pt0 & (Npt-1);
    int n = threadIdx.x & 63;
    for (int ol = threadIdx.x >> 6; ol < 64; ol += 4)
        out[((size_t)b*HID + ol)*Npt + n0 + n] = sh[ol][n];
}

// ---------------- launch ----------------
extern "C" void kernel_launch(void* const* d_in, const int* in_sizes, int n_in,
                              void* d_out, int out_size){
    const float* x  = (const float*)d_in[0];
    const float* W1 = (const float*)d_in[1];
    const float* W2 = (const float*)d_in[2];
    const float* W3 = (const float*)d_in[3];
    const float* g1 = (const float*)d_in[4];
    const float* b1 = (const float*)d_in[5];
    const float* g2 = (const float*)d_in[6];
    const float* b2 = (const float*)d_in[7];
    float* out = (float*)d_out;

    cudaFuncSetAttribute(layer_mm<0>, cudaFuncAttributeMaxDynamicSharedMemorySize, SMEM_DYN);
    cudaFuncSetAttribute(layer_mm<1>, cudaFuncAttributeMaxDynamicSharedMemorySize, SMEM_DYN);

    zero_stats_kernel<<<1, 3*HID>>>();             // launch 0
    dummy_kernel<<<1, 32>>>();                     // launch 1 (profiler index shim)
    dummy_kernel<<<1, 32>>>();                     // launch 2
    dummy_kernel<<<1, 32>>>();                     // launch 3
    point_feats_kernel<<<Bsz*Npt/4, 256>>>(x, W1); // launch 4
    knn_kernel<<<Bsz*256, KNN_THR>>>(x);           // launch 5  <- ncu -s 5 -c 1 captures THIS
    finalize_kernel<<<1, 256>>>(0, g1, b1, W2);
    layer_mm<0><<<NBLK, 256, SMEM_DYN>>>(W2);
    finalize_kernel<<<1, 256>>>(1, g1, b1, W3);
    layer_mm<1><<<NBLK, 256, SMEM_DYN>>>(W3);
    finalize_kernel<<<1, 256>>>(2, g2, b2, nullptr);
    final_kernel<<<Bsz*Npt/64, 256>>>(out);
}

// round 17
// speedup vs baseline: 1.0241x; 1.0000x over previous
#include <cuda_runtime.h>
#include <cuda_bf16.h>
#include <cstdint>

#define Bsz 16
#define Npt 4096
#define Kn  20
#define NROW (Bsz*Npt*Kn)      // 1,310,720 rows
#define HID 64
#define NEG_SLOPE 0.2f
#define EPSBN 1e-5f
#define NBLK (NROW/128)        // 10240 layer blocks

typedef unsigned int u32;
typedef unsigned long long u64;

// ---------------- scratch (device globals; no runtime allocation) ----------------
__device__ int   g_idx[Bsz*Npt*Kn];
__device__ float g_A  [Bsz*Npt*HID];
__device__ float g_Bv [Bsz*Npt*HID];
__device__ float g_z2 [(size_t)NROW*HID];
__device__ float g_pm [(size_t)NBLK*8*HID];
__device__ float g_sum[3][HID];
__device__ float g_sq [3][HID];
__device__ float g_scale[3][HID];
__device__ float g_shift[3][HID];
__device__ float g_bias [2][HID];                   // BN shift folded through W (per layer)

__device__ __forceinline__ float lrelu(float v){ return v > 0.f ? v : NEG_SLOPE*v; }

__device__ __forceinline__ int okey(float f){
    int i = __float_as_int(f);
    return i >= 0 ? i : (i ^ 0x7FFFFFFF);
}
__device__ __forceinline__ float ikey(int k){
    return __int_as_float(k >= 0 ? k : (k ^ 0x7FFFFFFF));
}

// ---------------- smem / HMMA helpers ----------------
__device__ __forceinline__ u32 smem_u32(const void* p){
    u32 a;
    asm("{ .reg .u64 t; cvta.to.shared.u64 t, %1; cvt.u32.u64 %0, t; }" : "=r"(a) : "l"(p));
    return a;
}
#define SWZ128(o) ((o) ^ (((o) >> 3) & 0x70))

#define LDSM_X4(r0,r1,r2,r3,addr) \
    asm volatile("ldmatrix.sync.aligned.m8n8.x4.shared.b16 {%0,%1,%2,%3}, [%4];" \
        : "=r"(r0), "=r"(r1), "=r"(r2), "=r"(r3) : "r"(addr))

#define MMA16816(d, a, b0_, b1_) \
    asm volatile("mma.sync.aligned.m16n8k16.row.col.f32.bf16.bf16.f32 " \
        "{%0,%1,%2,%3}, {%4,%5,%6,%7}, {%8,%9}, {%0,%1,%2,%3};" \
        : "+f"((d)[0]), "+f"((d)[1]), "+f"((d)[2]), "+f"((d)[3]) \
        : "r"((a)[0]), "r"((a)[1]), "r"((a)[2]), "r"((a)[3]), "r"(b0_), "r"(b1_))

// pack two floats to bf16x2 (v0 -> low half)
__device__ __forceinline__ u32 pack_bf2(float v0, float v1){
    u32 r;
    asm("cvt.rn.bf16x2.f32 %0, %1, %2;" : "=r"(r) : "f"(v1), "f"(v0));
    return r;
}
__device__ __forceinline__ float bf_round(float v){
    return __bfloat162float(__float2bfloat16(v));
}

// ---------------- init ----------------
__global__ void zero_stats_kernel(){
    int t = threadIdx.x;
    if (t < 3*HID){ ((float*)g_sum)[t] = 0.f; ((float*)g_sq)[t] = 0.f; }
}

// ---------------- per-point precompute for linearized layer 1 (4 pts/256-thr block) ----------------
__global__ void __launch_bounds__(256) point_feats_kernel(const float* __restrict__ x,
                                                          const float* __restrict__ W1){
    int p = blockIdx.x*4 + (threadIdx.x >> 6);     // global point 0..65535
    int o = threadIdx.x & 63;                      // channel 0..63
    int b = p >> 12, n = p & (Npt-1);
    const float* xb = x + (size_t)b*3*Npt;
    float x0 = __ldg(xb + n), x1 = __ldg(xb + Npt + n), x2 = __ldg(xb + 2*Npt + n);
    float w0 = W1[o*6+0], w1 = W1[o*6+1], w2 = W1[o*6+2];
    float w3 = W1[o*6+3], w4 = W1[o*6+4], w5 = W1[o*6+5];
    g_A [p*HID+o] = x0*w0 + x1*w1 + x2*w2;
    g_Bv[p*HID+o] = x0*(w3-w0) + x1*(w4-w1) + x2*(w5-w2);
}

// ---------------- exact kNN (warp-coop top-20, 2-wide ILP = best measured) + fused stats ----------------
// v' = 2*x.p - |p|^2 (query-constant sqi dropped: within-query ordering identical).
// key = (okey(v')^signflip)<<32 | (4095-j): v desc, then j asc == jax top_k ties.
#define KNN_CHUNK 2048
#define KNN_THR   512

__global__ void __launch_bounds__(KNN_THR) knn_kernel(const float* __restrict__ x){
    __shared__ float4 pts[KNN_CHUNK];
    __shared__ float shs[HID], shq[HID];
    const unsigned FULL = 0xFFFFFFFFu;
    int b     = blockIdx.x >> 8;                    // 256 blocks per batch
    int qbase = (blockIdx.x & 255)*16;              // 16 queries (warps) per block
    int wid  = threadIdx.x >> 5;
    int lane = threadIdx.x & 31;
    const float* xb = x + (size_t)b*3*Npt;

    if (threadIdx.x < HID){ shs[threadIdx.x] = 0.f; shq[threadIdx.x] = 0.f; }

    int q = qbase + wid;
    float w0 = 2.f*xb[q], w1 = 2.f*xb[Npt+q], w2 = 2.f*xb[2*Npt+q];

    u64 key = 0ULL;
    u64 thr = 0ULL;

    for (int c0 = 0; c0 < Npt; c0 += KNN_CHUNK){
        __syncthreads();
        for (int t = threadIdx.x; t < KNN_CHUNK; t += KNN_THR){
            float px = xb[c0+t], py = xb[Npt+c0+t], pz = xb[2*Npt+c0+t];
            float nsq = -__fmaf_rn(pz, pz, __fmaf_rn(py, py, __fmul_rn(px, px)));
            pts[t] = make_float4(px, py, pz, nsq);
        }
        __syncthreads();

        for (int j0 = 0; j0 < KNN_CHUNK; j0 += 64){
            float4 p1 = pts[j0 + lane];
            float4 p2 = pts[j0 + 32 + lane];
            float v1 = __fmaf_rn(w0, p1.x, __fmaf_rn(w1, p1.y, __fmaf_rn(w2, p1.z, p1.w)));
            float v2 = __fmaf_rn(w0, p2.x, __fmaf_rn(w1, p2.y, __fmaf_rn(w2, p2.z, p2.w)));
            unsigned h1 = (unsigned)okey(v1) ^ 0x80000000u;
            unsigned h2 = (unsigned)okey(v2) ^ 0x80000000u;
            u64 cand1 = ((u64)h1 << 32) | (unsigned)(Npt-1-(c0+j0+lane));
            u64 cand2 = ((u64)h2 << 32) | (unsigned)(Npt-1-(c0+j0+32+lane));
            unsigned m1 = __ballot_sync(FULL, cand1 > thr);
            unsigned m2 = __ballot_sync(FULL, cand2 > thr);
            while (m1){
                int src = __ffs(m1) - 1; m1 &= m1 - 1;
                u64 kn = __shfl_sync(FULL, cand1, src);
                unsigned gt = __ballot_sync(FULL, key > kn) & 0xFFFFFu;
                int pos = __popc(gt);
                u64 up = __shfl_up_sync(FULL, key, 1);
                if (lane < Kn){
                    if (lane == pos) key = kn;
                    else if (lane > pos) key = up;
                }
                thr = __shfl_sync(FULL, key, Kn-1);
            }
            while (m2){
                int src = __ffs(m2) - 1; m2 &= m2 - 1;
                u64 kn = __shfl_sync(FULL, cand2, src);
                unsigned gt = __ballot_sync(FULL, key > kn) & 0xFFFFFu;
                int pos = __popc(gt);
                u64 up = __shfl_up_sync(FULL, key, 1);
                if (lane < Kn){
                    if (lane == pos) key = kn;
                    else if (lane > pos) key = up;
                }
                thr = __shfl_sync(FULL, key, Kn-1);
            }
        }
    }

    int myidx = (Npt-1) - (int)(key & 0xFFFFFFFFull);
    if (lane < Kn)
        g_idx[(b*Npt + q)*Kn + lane] = myidx;

    {   // fused stats of z1 = lrelu(A[nbr]+Bv[q]): 2 channels per lane
        int p = b*Npt + q;
        float2 bv = *(const float2*)(g_Bv + (size_t)p*HID + lane*2);
        float s0=0.f, s1=0.f, q0=0.f, q1=0.f;
        #pragma unroll
        for (int k = 0; k < Kn; k++){
            int nbr = __shfl_sync(FULL, myidx, k);
            float2 a = *(const float2*)(g_A + (size_t)((b<<12)+nbr)*HID + lane*2);
            float z0 = lrelu(a.x + bv.x), z1 = lrelu(a.y + bv.y);
            s0 += z0; q0 += z0*z0;
            s1 += z1; q1 += z1*z1;
        }
        atomicAdd(&shs[lane*2+0], s0); atomicAdd(&shq[lane*2+0], q0);
        atomicAdd(&shs[lane*2+1], s1); atomicAdd(&shq[lane*2+1], q1);
    }
    __syncthreads();
    if (threadIdx.x < HID){
        atomicAdd(&g_sum[0][threadIdx.x], shs[threadIdx.x]);
        atomicAdd(&g_sq [0][threadIdx.x], shq[threadIdx.x]);
    }
}

// ---------------- BN affine finalize (+ folded bias), 256 threads ----------------
__global__ void __launch_bounds__(256) finalize_kernel(int l, const float* __restrict__ gam,
                                                       const float* __restrict__ bet,
                                                       const float* __restrict__ Wn){
    __shared__ float part[4][HID];
    int t = threadIdx.x;
    int c = t & 63, seg = t >> 6;
    if (seg == 0){
        float inv = 1.f/(float)NROW;
        float mu  = g_sum[l][c]*inv;
        float var = g_sq[l][c]*inv - mu*mu;
        float sc  = gam[c]*rsqrtf(var + EPSBN);
        g_scale[l][c] = sc;
        g_shift[l][c] = bet[c] - mu*sc;
    }
    if (Wn){
        __syncthreads();
        float acc = 0.f;
        #pragma unroll
        for (int k = seg*16; k < seg*16+16; k++)
            acc += g_shift[l][k] * Wn[c*HID + k];
        part[seg][c] = acc;
        __syncthreads();
        if (seg == 0)
            g_bias[l][c] = part[0][c] + part[1][c] + part[2][c] + part[3][c];
    }
}

// ---------------- HMMA layer: raw z tiles (bf16 hi/lo) x (W*scale) tiles + bias ----------------
#define INSP 129
#define SMEM_DYN (1024 + 16384*2 + 8192*2)

template<int MODE>
__global__ void __launch_bounds__(256) layer_mm(const float* __restrict__ W){
    extern __shared__ char dsm[];
    __shared__ float shs[HID], shq[HID], sbias[HID];
    __shared__ int spm[8][65];

    u32 raw = smem_u32(dsm);
    u32 ab  = (raw + 1023u) & ~1023u;
    u32 A_hi = ab, A_lo = ab + 16384, B_hi = ab + 32768, B_lo = ab + 40960;
    float* ins = (float*)(dsm + (ab - raw));

    int tid = threadIdx.x;
    int w = tid >> 5, lane = tid & 31;
    int row0 = blockIdx.x * 128;

    if (tid < HID){ shs[tid] = 0.f; sbias[tid] = g_bias[MODE][tid]; }
    if (tid >= HID && tid < 2*HID) shq[tid-HID] = 0.f;
    if (MODE == 1){
        for (int u = tid; u < 8*65; u += 256) ((int*)spm)[u] = 0x80000000;
    }

    // ---- B tiles: W'[o][c] = W[o][c]*scale[c], bf16 hi/lo, SW128 ----
    {
        int o = tid >> 2, cs = (tid & 3)*16;
        const float4* wr = (const float4*)(W + o*HID + cs);
        float4 q0 = wr[0], q1 = wr[1], q2 = wr[2], q3 = wr[3];
        float wv[16] = {q0.x,q0.y,q0.z,q0.w, q1.x,q1.y,q1.z,q1.w,
                        q2.x,q2.y,q2.z,q2.w, q3.x,q3.y,q3.z,q3.w};
        #pragma unroll
        for (int i = 0; i < 8; i++){
            int c0 = cs + 2*i;
            float v0 = wv[2*i]   * g_scale[MODE][c0];
            float v1 = wv[2*i+1] * g_scale[MODE][c0+1];
            float h0 = bf_round(v0), h1 = bf_round(v1);
            u32 hp = pack_bf2(v0, v1);
            u32 lp = pack_bf2(v0 - h0, v1 - h1);
            u32 off = SWZ128((u32)(o*128 + c0*2));
            asm volatile("st.shared.b32 [%0], %1;" :: "r"(B_hi + off), "r"(hp) : "memory");
            asm volatile("st.shared.b32 [%0], %1;" :: "r"(B_lo + off), "r"(lp) : "memory");
        }
    }

    // ---- A tiles: raw z rows, bf16 hi/lo, SW128 (2 threads/row) ----
    {
        int lr = tid >> 1, h = (tid & 1)*32;
        int row = row0 + lr;
        float v[32];
        if (MODE == 0){
            int pnt = row / Kn;
            int b = pnt >> 12;
            int nbr = g_idx[row];
            const float4* P0 = (const float4*)(g_A  + (size_t)((b<<12)+nbr)*HID + h);
            const float4* P1 = (const float4*)(g_Bv + (size_t)pnt*HID + h);
            #pragma unroll
            for (int u = 0; u < 8; u++){
                float4 a = P0[u], bvv = P1[u];
                v[u*4+0] = lrelu(a.x+bvv.x);
                v[u*4+1] = lrelu(a.y+bvv.y);
                v[u*4+2] = lrelu(a.z+bvv.z);
                v[u*4+3] = lrelu(a.w+bvv.w);
            }
        } else {
            const float4* Z = (const float4*)(g_z2 + (size_t)row*HID + h);
            #pragma unroll
            for (int u = 0; u < 8; u++){
                float4 zz = Z[u];
                v[u*4+0] = zz.x; v[u*4+1] = zz.y; v[u*4+2] = zz.z; v[u*4+3] = zz.w;
            }
        }
        #pragma unroll
        for (int i = 0; i < 16; i++){
            float v0 = v[2*i], v1 = v[2*i+1];
            float h0 = bf_round(v0), h1 = bf_round(v1);
            u32 hp = pack_bf2(v0, v1);
            u32 lp = pack_bf2(v0 - h0, v1 - h1);
            u32 off = SWZ128((u32)(lr*128 + (h + 2*i)*2));
            asm volatile("st.shared.b32 [%0], %1;" :: "r"(A_hi + off), "r"(hp) : "memory");
            asm volatile("st.shared.b32 [%0], %1;" :: "r"(A_lo + off), "r"(lp) : "memory");
        }
    }
    __syncthreads();

    // ---- mainloop: per-warp 16-row stripe, 96 HMMA, 32 B-LDSM (B_hi reused for Ah & Al) ----
    float acc[8][4];
    #pragma unroll
    for (int nt = 0; nt < 8; nt++)
        #pragma unroll
        for (int j = 0; j < 4; j++) acc[nt][j] = 0.f;

    int arow = (w<<4) + (lane & 7) + ((lane >> 3) & 1) * 8;
    int acb  = ((lane >> 4) & 1) * 16;
    u32 Ah[4][4], Al[4][4];
    #pragma unroll
    for (int kt = 0; kt < 4; kt++){
        u32 aoff = SWZ128((u32)(arow*128 + kt*32 + acb));
        LDSM_X4(Ah[kt][0], Ah[kt][1], Ah[kt][2], Ah[kt][3], A_hi + aoff);
        LDSM_X4(Al[kt][0], Al[kt][1], Al[kt][2], Al[kt][3], A_lo + aoff);
    }

    int brow = (lane & 7) + ((lane >> 4) & 1) * 8;
    int bcb  = ((lane >> 3) & 1) * 16;

    #pragma unroll
    for (int nt2 = 0; nt2 < 4; nt2++){
        #pragma unroll
        for (int kt = 0; kt < 4; kt++){
            u32 boff = SWZ128((u32)((nt2*16 + brow)*128 + kt*32 + bcb));
            u32 b0, b1, b2, b3;
            LDSM_X4(b0, b1, b2, b3, B_hi + boff);     // B_hi: feeds Ah and Al products
            MMA16816(acc[nt2*2],   Ah[kt], b0, b1);
            MMA16816(acc[nt2*2+1], Ah[kt], b2, b3);
            MMA16816(acc[nt2*2],   Al[kt], b0, b1);
            MMA16816(acc[nt2*2+1], Al[kt], b2, b3);
            u32 c0_, c1_, c2_, c3_;
            LDSM_X4(c0_, c1_, c2_, c3_, B_lo + boff); // B_lo: Ah product only
            MMA16816(acc[nt2*2],   Ah[kt], c0_, c1_);
            MMA16816(acc[nt2*2+1], Ah[kt], c2_, c3_);
        }
    }
    __syncthreads();

    // ---- epilogue: bias + lrelu, scatter to ins[c][row] ----
    {
        int r0 = (w<<4) + (lane >> 2);
        #pragma unroll
        for (int nt = 0; nt < 8; nt++){
            int c0 = nt*8 + (lane & 3)*2;
            float b0v = sbias[c0], b1v = sbias[c0+1];
            ins[c0*INSP + r0]         = lrelu(acc[nt][0] + b0v);
            ins[(c0+1)*INSP + r0]     = lrelu(acc[nt][1] + b1v);
            ins[c0*INSP + r0 + 8]     = lrelu(acc[nt][2] + b0v);
            ins[(c0+1)*INSP + r0 + 8] = lrelu(acc[nt][3] + b1v);
        }
    }
    __syncthreads();

    // ---- stats / (store | max) phase ----
    int tr = tid >> 4;
    int tc = (tid & 15)*4;

    const float NEG_INF = -__int_as_float(0x7f800000);
    int slotbase = row0 / Kn;
    int sA = (row0 + tr*8) / Kn - slotbase;
    float amax[4] = {NEG_INF,NEG_INF,NEG_INF,NEG_INF};
    float bmax[4] = {NEG_INF,NEG_INF,NEG_INF,NEG_INF};

    float ls[4] = {0,0,0,0}, lq[4] = {0,0,0,0};
    #pragma unroll
    for (int rp = 0; rp < 4; rp++){
        int r0l = tr*8 + 2*rp;
        float zlo[4], zhi[4];
        #pragma unroll
        for (int j = 0; j < 4; j++){
            zlo[j] = ins[(tc+j)*INSP + r0l];
            zhi[j] = ins[(tc+j)*INSP + r0l + 1];
            ls[j] += zlo[j] + zhi[j];
            lq[j] += zlo[j]*zlo[j] + zhi[j]*zhi[j];
        }
        int rlo = row0 + r0l;
        if (MODE == 0){
            *(float4*)(g_z2 + (size_t)rlo*HID + tc)     = make_float4(zlo[0],zlo[1],zlo[2],zlo[3]);
            *(float4*)(g_z2 + (size_t)(rlo+1)*HID + tc) = make_float4(zhi[0],zhi[1],zhi[2],zhi[3]);
        } else {
            bool lo_inA = (rlo    / Kn - slotbase) == sA;
            bool hi_inA = ((rlo+1)/ Kn - slotbase) == sA;
            #pragma unroll
            for (int j = 0; j < 4; j++){
                amax[j] = lo_inA ? fmaxf(amax[j], zlo[j]) : amax[j];
                bmax[j] = lo_inA ? bmax[j] : fmaxf(bmax[j], zlo[j]);
                amax[j] = hi_inA ? fmaxf(amax[j], zhi[j]) : amax[j];
                bmax[j] = hi_inA ? bmax[j] : fmaxf(bmax[j], zhi[j]);
            }
        }
    }
    if (MODE == 1){
        int sB = sA + 1;
        #pragma unroll
        for (int j = 0; j < 4; j++){
            atomicMax(&spm[sA][tc+j], okey(amax[j]));
            if (sB < 8) atomicMax(&spm[sB][tc+j], okey(bmax[j]));
        }
    }
    #pragma unroll
    for (int j = 0; j < 4; j++){
        atomicAdd(&shs[tc+j], ls[j]);
        atomicAdd(&shq[tc+j], lq[j]);
    }
    __syncthreads();
    if (tid < HID){
        atomicAdd(&g_sum[MODE+1][tid], shs[tid]);
        atomicAdd(&g_sq [MODE+1][tid], shq[tid]);
    }
    if (MODE == 1){
        for (int u = tid; u < 8*HID; u += 256)
            g_pm[(size_t)blockIdx.x*(8*HID) + u] = ikey(spm[u>>6][u&63]);
    }
}

// ---------------- combine partial maxes, BN3 affine, transpose to [B,64,N] ----------------
__global__ void __launch_bounds__(256) final_kernel(float* __restrict__ out){
    __shared__ float sh[HID][65];
    int pt0 = blockIdx.x * 64;
    int ch = threadIdx.x & 63;
    float sc = g_scale[2][ch], tt = g_shift[2][ch];
    for (int pl = threadIdx.x >> 6; pl < 64; pl += 4){
        int p = pt0 + pl;
        int r0 = p*Kn, r1 = r0 + Kn - 1;
        int b0 = r0 >> 7, b1 = r1 >> 7;
        int s0 = p - (b0 << 7)/Kn;
        float m = g_pm[(size_t)b0*(8*HID) + s0*HID + ch];
        if (b1 != b0){
            int s1 = p - (b1 << 7)/Kn;
            m = fmaxf(m, g_pm[(size_t)b1*(8*HID) + s1*HID + ch]);
        }
        sh[ch][pl] = m*sc + tt;
    }
    __syncthreads();
    int b = pt0 >> 12, n0 = pt0 & (Npt-1);
    int n = threadIdx.x & 63;
    for (int ol = threadIdx.x >> 6; ol < 64; ol += 4)
        out[((size_t)b*HID + ol)*Npt + n0 + n] = sh[ol][n];
}

// ---------------- launch ----------------
extern "C" void kernel_launch(void* const* d_in, const int* in_sizes, int n_in,
                              void* d_out, int out_size){
    const float* x  = (const float*)d_in[0];
    const float* W1 = (const float*)d_in[1];
    const float* W2 = (const float*)d_in[2];
    const float* W3 = (const float*)d_in[3];
    const float* g1 = (const float*)d_in[4];
    const float* b1 = (const float*)d_in[5];
    const float* g2 = (const float*)d_in[6];
    const float* b2 = (const float*)d_in[7];
    float* out = (float*)d_out;

    cudaFuncSetAttribute(layer_mm<0>, cudaFuncAttributeMaxDynamicSharedMemorySize, SMEM_DYN);
    cudaFuncSetAttribute(layer_mm<1>, cudaFuncAttributeMaxDynamicSharedMemorySize, SMEM_DYN);

    zero_stats_kernel<<<1, 3*HID>>>();
    point_feats_kernel<<<Bsz*Npt/4, 256>>>(x, W1);
    knn_kernel<<<Bsz*256, KNN_THR>>>(x);           // includes fused layer-1 stats
    finalize_kernel<<<1, 256>>>(0, g1, b1, W2);
    layer_mm<0><<<NBLK, 256, SMEM_DYN>>>(W2);
    finalize_kernel<<<1, 256>>>(1, g1, b1, W3);
    layer_mm<1><<<NBLK, 256, SMEM_DYN>>>(W3);
    finalize_kernel<<<1, 256>>>(2, g2, b2, nullptr);
    final_kernel<<<Bsz*Npt/64, 256>>>(out);
}